// round 9
// baseline (speedup 1.0000x reference)
#include <cuda_runtime.h>
#include <cuda_bf16.h>
#include <math.h>
#include <cstdint>
#include <cstring>

// ---------------------------------------------------------------------------
// MLA attention pipeline. B=4, T=2048, D=512, H=8, KVH=2, HD=64
// Round 9: GEMM fusion by weight-row concatenation (shared-A groups):
//   X-group  (DQ|DKV|KR|VR): N=960, K=512  -> 960 blocks
//   CQ-group (UQ|QR):        N=512, K=256  -> 512 blocks
//   CKV-group(UK|UV):        N=192, K=128  -> 192 blocks
//   WO:                      N=512, K=512  -> 512 blocks
// Fixes the grid-starvation ncu showed (64-block launches on 148 SMs).
// ---------------------------------------------------------------------------

#define Bb   4
#define Tt   2048
#define Hh   8
#define KVHh 2
#define BT   (Bb*Tt)      // 8192
#define EPSF 1e-6f

// ------------------------- scratch (device globals) ------------------------
__device__ float g_xout[BT*960];   // cq|ckv|kr|vres  (cols 0|256|384|448)
__device__ float g_q2  [BT*512];   // qn|qr
__device__ float g_kv2 [BT*192];   // kn|vraw
__device__ float g_q   [BT*512];   // [B,H,T,64] fp32
__device__ float g_ao  [BT*512];

__device__ __nv_bfloat16 g_khi[Bb*KVHh*Tt*64];
__device__ __nv_bfloat16 g_klo[Bb*KVHh*Tt*64];
__device__ __nv_bfloat16 g_vhi[Bb*KVHh*Tt*64];
__device__ __nv_bfloat16 g_vlo[Bb*KVHh*Tt*64];

__device__ __nv_bfloat16 g_ahi[BT*512];
__device__ __nv_bfloat16 g_alo[BT*512];

// fused weight groups, [N][K] row-stacked
#define OFF_X    0
#define OFF_DQ   0
#define OFF_DKV  131072     // row 256 * 512
#define OFF_KR   196608     // row 384 * 512
#define OFF_VR   229376     // row 448 * 512
#define OFF_CQ   491520     // 960*512
#define OFF_UQ   491520
#define OFF_QR   557056     // +256*256
#define OFF_CKV  622592     // +512*256
#define OFF_UK   622592
#define OFF_UV   630784     // +64*128
#define OFF_WO   647168     // +192*128
#define WT_TOT   909312
__device__ __nv_bfloat16 g_whi[WT_TOT];
__device__ __nv_bfloat16 g_wlo[WT_TOT];

// ------------------------- PTX helpers -------------------------------------
__device__ __forceinline__ void mma16816(
    float* d, const uint32_t* a, const uint32_t* b)
{
    asm volatile(
        "mma.sync.aligned.m16n8k16.row.col.f32.bf16.bf16.f32 "
        "{%0,%1,%2,%3}, {%4,%5,%6,%7}, {%8,%9}, {%0,%1,%2,%3};"
        : "+f"(d[0]), "+f"(d[1]), "+f"(d[2]), "+f"(d[3])
        : "r"(a[0]), "r"(a[1]), "r"(a[2]), "r"(a[3]), "r"(b[0]), "r"(b[1]));
}

__device__ __forceinline__ void ldsm4(uint32_t* r, uint32_t addr) {
    asm volatile("ldmatrix.sync.aligned.m8n8.x4.shared.b16 {%0,%1,%2,%3}, [%4];"
        : "=r"(r[0]), "=r"(r[1]), "=r"(r[2]), "=r"(r[3]) : "r"(addr));
}
__device__ __forceinline__ void ldsm4t(uint32_t* r, uint32_t addr) {
    asm volatile("ldmatrix.sync.aligned.m8n8.x4.trans.shared.b16 {%0,%1,%2,%3}, [%4];"
        : "=r"(r[0]), "=r"(r[1]), "=r"(r[2]), "=r"(r[3]) : "r"(addr));
}

__device__ __forceinline__ uint32_t smem_u32(const void* p) {
    uint32_t a;
    asm("{ .reg .u64 t; cvta.to.shared.u64 t, %1; cvt.u32.u64 %0, t; }"
        : "=r"(a) : "l"(p));
    return a;
}

__device__ __forceinline__ uint32_t pack_bf16(float lo, float hi) {
    __nv_bfloat162 p = __floats2bfloat162_rn(lo, hi);
    uint32_t u; memcpy(&u, &p, 4);
    return u;
}

// ---------------------------------------------------------------------------
// Batched transpose + bf16 hi/lo split: 9 weights in one launch.
// ---------------------------------------------------------------------------
struct TJobs {
    const float* W[9];
    int K[9], N[9], woff[9];
    int t0[10];
};

__global__ void transpose_split_all(
    TJobs jb, __nv_bfloat16* __restrict__ hi, __nv_bfloat16* __restrict__ lo)
{
    __shared__ float t[32][33];
    const int bid = blockIdx.x;
    int j = 0;
    #pragma unroll
    for (int i = 0; i < 8; ++i) if (bid >= jb.t0[i + 1]) j = i + 1;
    const int tile = bid - jb.t0[j];
    const int K = jb.K[j], N = jb.N[j];
    const int ntx = N / 32;
    const int n0 = (tile % ntx) * 32, k0 = (tile / ntx) * 32;
    const float* W = jb.W[j];
    __nv_bfloat16* ho = hi + jb.woff[j];
    __nv_bfloat16* lp = lo + jb.woff[j];

    for (int r = threadIdx.y; r < 32; r += 8)
        t[r][threadIdx.x] = W[(size_t)(k0 + r) * N + n0 + threadIdx.x];
    __syncthreads();
    for (int r = threadIdx.y; r < 32; r += 8) {
        float v = t[threadIdx.x][r];
        __nv_bfloat16 h = __float2bfloat16(v);
        __nv_bfloat16 l = __float2bfloat16(v - __bfloat162float(h));
        ho[(size_t)(n0 + r) * K + k0 + threadIdx.x] = h;
        lp[(size_t)(n0 + r) * K + k0 + threadIdx.x] = l;
    }
}

// ---------------------------------------------------------------------------
// fp32 -> bf16 hi/lo split, compact input.
// ---------------------------------------------------------------------------
__global__ __launch_bounds__(256) void split_act(
    const float* __restrict__ x, __nv_bfloat16* __restrict__ hi,
    __nv_bfloat16* __restrict__ lo)
{
    const size_t job = (size_t)blockIdx.x * 256 + threadIdx.x;
    float4 v = *(const float4*)(x + job * 4);
    float h0 = __bfloat162float(__float2bfloat16(v.x));
    float h1 = __bfloat162float(__float2bfloat16(v.y));
    float h2 = __bfloat162float(__float2bfloat16(v.z));
    float h3 = __bfloat162float(__float2bfloat16(v.w));
    uint2 ph = make_uint2(pack_bf16(h0, h1), pack_bf16(h2, h3));
    uint2 pl = make_uint2(pack_bf16(v.x - h0, v.y - h1), pack_bf16(v.z - h2, v.w - h3));
    *(uint2*)((uint32_t*)hi + job * 2) = ph;
    *(uint2*)((uint32_t*)lo + job * 2) = pl;
}

// strided slice variant: src row stride `stride`, slice [col0, col0+dim);
// output compact [rows][dim].
__global__ __launch_bounds__(256) void split_act_strided(
    const float* __restrict__ src, int stride, int col0, int dim,
    __nv_bfloat16* __restrict__ hi, __nv_bfloat16* __restrict__ lo)
{
    const size_t job = (size_t)blockIdx.x * 256 + threadIdx.x;
    const size_t idx = job * 4;
    const int row = (int)(idx / dim), col = (int)(idx % dim);
    float4 v = *(const float4*)(src + (size_t)row * stride + col0 + col);
    float h0 = __bfloat162float(__float2bfloat16(v.x));
    float h1 = __bfloat162float(__float2bfloat16(v.y));
    float h2 = __bfloat162float(__float2bfloat16(v.z));
    float h3 = __bfloat162float(__float2bfloat16(v.w));
    uint2 ph = make_uint2(pack_bf16(h0, h1), pack_bf16(h2, h3));
    uint2 pl = make_uint2(pack_bf16(v.x - h0, v.y - h1), pack_bf16(v.z - h2, v.w - h3));
    *(uint2*)((uint32_t*)hi + job * 2) = ph;
    *(uint2*)((uint32_t*)lo + job * 2) = pl;
}

// ---------------------------------------------------------------------------
// HMMA GEMM (verified R8 kernel, unchanged math).
// ---------------------------------------------------------------------------
template <int BN>
__global__ __launch_bounds__(256) void hgemm(
    const __nv_bfloat16* __restrict__ Ahi, const __nv_bfloat16* __restrict__ Alo,
    const __nv_bfloat16* __restrict__ Whi, const __nv_bfloat16* __restrict__ Wlo,
    float* __restrict__ C, int M, int N, int K)
{
    __shared__ uint32_t sBhi[BN * 36];
    __shared__ uint32_t sBlo[BN * 36];

    const int bm = blockIdx.y * 128;
    const int bn = blockIdx.x * BN;
    const int tid = threadIdx.x;
    const int w = tid >> 5, lane = tid & 31;
    const int g = lane >> 2, t = lane & 3;
    constexpr int NT = BN / 8;
    constexpr int NJ = BN / 32;

    const uint32_t bH = smem_u32(sBhi);
    const uint32_t bL = smem_u32(sBlo);
    const int lrow = (lane & 7) * 36;
    const int lm   = (lane >> 3) * 4;

    float acc[NT][4];
    #pragma unroll
    for (int nt = 0; nt < NT; ++nt)
        #pragma unroll
        for (int j = 0; j < 4; ++j) acc[nt][j] = 0.f;

    const int r0 = bm + w * 16 + g;

    int jn[NJ], jc[NJ];
    #pragma unroll
    for (int i = 0; i < NJ; ++i) { int j = tid + i * 256; jn[i] = j >> 3; jc[i] = j & 7; }

    uint4 pfh[NJ], pfl[NJ];
    #pragma unroll
    for (int i = 0; i < NJ; ++i) {
        size_t go = (size_t)(bn + jn[i]) * K + jc[i] * 8;
        pfh[i] = *(const uint4*)(Whi + go);
        pfl[i] = *(const uint4*)(Wlo + go);
    }

    const int nchunk = K >> 6;
    for (int ch = 0; ch < nchunk; ++ch) {
        __syncthreads();
        #pragma unroll
        for (int i = 0; i < NJ; ++i) {
            *(uint4*)&sBhi[jn[i] * 36 + jc[i] * 4] = pfh[i];
            *(uint4*)&sBlo[jn[i] * 36 + jc[i] * 4] = pfl[i];
        }
        __syncthreads();
        if (ch + 1 < nchunk) {
            #pragma unroll
            for (int i = 0; i < NJ; ++i) {
                size_t go = (size_t)(bn + jn[i]) * K + (ch + 1) * 64 + jc[i] * 8;
                pfh[i] = *(const uint4*)(Whi + go);
                pfl[i] = *(const uint4*)(Wlo + go);
            }
        }

        uint32_t ahi[4][4], alo[4][4];
        {
            const size_t base0 = (size_t)r0 * K + ch * 64;
            const size_t base1 = base0 + 8 * (size_t)K;
            #pragma unroll
            for (int ks = 0; ks < 4; ++ks) {
                int c = ks * 16 + 2 * t;
                ahi[ks][0] = *(const uint32_t*)(Ahi + base0 + c);
                ahi[ks][1] = *(const uint32_t*)(Ahi + base1 + c);
                ahi[ks][2] = *(const uint32_t*)(Ahi + base0 + c + 8);
                ahi[ks][3] = *(const uint32_t*)(Ahi + base1 + c + 8);
                alo[ks][0] = *(const uint32_t*)(Alo + base0 + c);
                alo[ks][1] = *(const uint32_t*)(Alo + base1 + c);
                alo[ks][2] = *(const uint32_t*)(Alo + base0 + c + 8);
                alo[ks][3] = *(const uint32_t*)(Alo + base1 + c + 8);
            }
        }

        #pragma unroll
        for (int nt = 0; nt < NT; ++nt) {
            uint32_t bh[8], bl[8];
            const int wo = nt * 288 + lrow + lm;
            ldsm4(bh,     bH + wo * 4);
            ldsm4(bh + 4, bH + (wo + 16) * 4);
            ldsm4(bl,     bL + wo * 4);
            ldsm4(bl + 4, bL + (wo + 16) * 4);
            #pragma unroll
            for (int ks = 0; ks < 4; ++ks) {
                mma16816(acc[nt], ahi[ks], bh + 2 * ks);
                mma16816(acc[nt], alo[ks], bh + 2 * ks);
                mma16816(acc[nt], ahi[ks], bl + 2 * ks);
            }
        }
    }

    #pragma unroll
    for (int nt = 0; nt < NT; ++nt) {
        const int col = bn + nt * 8 + 2 * t;
        *(float2*)(C + (size_t)r0 * N + col)       = make_float2(acc[nt][0], acc[nt][1]);
        *(float2*)(C + (size_t)(r0 + 8) * N + col) = make_float2(acc[nt][2], acc[nt][3]);
    }
}

// ---------------------------------------------------------------------------
// In-place strided RMSNorm: rows at x + row*stride + col0, length dim.
// ---------------------------------------------------------------------------
__global__ __launch_bounds__(128) void rms_strided(
    float* __restrict__ x, const float* __restrict__ w,
    int dim, int stride, int col0)
{
    const int row = blockIdx.x;
    float* xr = x + (size_t)row * stride + col0;
    float ss = 0.f;
    for (int i = threadIdx.x; i < dim; i += 128) { float v = xr[i]; ss += v * v; }
    #pragma unroll
    for (int off = 16; off; off >>= 1) ss += __shfl_xor_sync(0xffffffffu, ss, off);
    __shared__ float sred[4];
    if ((threadIdx.x & 31) == 0) sred[threadIdx.x >> 5] = ss;
    __syncthreads();
    float tot = sred[0] + sred[1] + sred[2] + sred[3];
    float rr = rsqrtf(tot / (float)dim + EPSF);
    for (int i = threadIdx.x; i < dim; i += 128) xr[i] = xr[i] * rr * w[i];
}

// ---------------------------------------------------------------------------
// Assemble: RoPE + concat + per-head RMSNorm; reads fused strided buffers.
// q2: [BT][512] = qn|qr ; kv2: [BT][192] = kn|vraw ; xout col 384: kr.
// ---------------------------------------------------------------------------
__global__ __launch_bounds__(256) void assemble(
    const float* __restrict__ q2, const float* __restrict__ kv2,
    const float* __restrict__ xout,
    const float* __restrict__ qhw, const float* __restrict__ khw,
    float* __restrict__ q,
    __nv_bfloat16* __restrict__ khi, __nv_bfloat16* __restrict__ klo,
    __nv_bfloat16* __restrict__ vhi, __nv_bfloat16* __restrict__ vlo)
{
    const int t = blockIdx.x, b = blockIdx.y;
    const int row = b * Tt + t;
    const int w = threadIdx.x >> 5, lane = threadIdx.x & 31;

    const int fi = lane & 15;
    float invf = (float)exp(-((double)fi / 16.0) * log(500000.0));
    float ph = (float)t * invf;
    float sv, cv;
    sincosf(ph, &sv, &cv);

    {
        const int h = w;
        const float* qnr = q2 + (size_t)row * 512 + h * 32;
        const float* qrr = q2 + (size_t)row * 512 + 256 + h * 32;
        float v0 = qnr[lane];
        float x1 = qrr[lane];
        float xr_ = (lane < 16) ? -qrr[lane + 16] : qrr[lane - 16];
        float v1 = x1 * cv + xr_ * sv;
        float ss = v0 * v0 + v1 * v1;
        #pragma unroll
        for (int off = 16; off; off >>= 1) ss += __shfl_xor_sync(0xffffffffu, ss, off);
        float rr = rsqrtf(ss / 64.0f + EPSF);
        float* qo = q + ((size_t)(b * Hh + h) * Tt + t) * 64;
        qo[lane]      = v0 * rr * qhw[lane];
        qo[lane + 32] = v1 * rr * qhw[lane + 32];
    }

    if (w < KVHh) {
        const int kvh = w;
        const float* knr = kv2 + (size_t)row * 192 + kvh * 32;
        const float* krr = xout + (size_t)row * 960 + 384 + kvh * 32;
        float v0 = knr[lane];
        float x1 = krr[lane];
        float xr_ = (lane < 16) ? -krr[lane + 16] : krr[lane - 16];
        float v1 = x1 * cv + xr_ * sv;
        float ss = v0 * v0 + v1 * v1;
        #pragma unroll
        for (int off = 16; off; off >>= 1) ss += __shfl_xor_sync(0xffffffffu, ss, off);
        float rr = rsqrtf(ss / 64.0f + EPSF);
        float k0 = v0 * rr * khw[lane];
        float k1 = v1 * rr * khw[lane + 32];
        size_t ko = ((size_t)(b * KVHh + kvh) * Tt + t) * 64;
        float h0 = __bfloat162float(__float2bfloat16(k0));
        float h1 = __bfloat162float(__float2bfloat16(k1));
        khi[ko + lane]      = __float2bfloat16(h0);
        khi[ko + lane + 32] = __float2bfloat16(h1);
        klo[ko + lane]      = __float2bfloat16(k0 - h0);
        klo[ko + lane + 32] = __float2bfloat16(k1 - h1);
    }

    for (int i = threadIdx.x; i < 128; i += 256) {
        int kvh = i >> 6, d = i & 63;
        float val = kv2[(size_t)row * 192 + 64 + i];
        float h = __bfloat162float(__float2bfloat16(val));
        size_t o = ((size_t)(b * KVHh + kvh) * Tt + t) * 64 + d;
        vhi[o] = __float2bfloat16(h);
        vlo[o] = __float2bfloat16(val - h);
    }
}

// ---------------------------------------------------------------------------
// Flash attention on HMMA, ldmatrix fragments (verified R8 kernel).
// vres now lives in xout cols [448, 960). Grid (T/64, H, B), 128 thr.
// ---------------------------------------------------------------------------
__global__ __launch_bounds__(128) void flash_mma(
    const float* __restrict__ Q,
    const __nv_bfloat16* __restrict__ Khi, const __nv_bfloat16* __restrict__ Klo,
    const __nv_bfloat16* __restrict__ Vhi, const __nv_bfloat16* __restrict__ Vlo,
    const float* __restrict__ xout, float* __restrict__ out)
{
    __shared__ uint32_t sKhi[64 * 36];
    __shared__ uint32_t sKlo[64 * 36];
    __shared__ uint32_t sVhi[64 * 36];
    __shared__ uint32_t sVlo[64 * 36];

    const int qt = (Tt / 64 - 1) - blockIdx.x;
    const int h = blockIdx.y, b = blockIdx.z;
    const int kvh = h >> 2;
    const float* qbase = Q + (((size_t)b * Hh + h) * Tt + qt * 64) * 64;
    const size_t kvbase = ((size_t)(b * KVHh + kvh) * Tt) * 64;

    const int tid  = threadIdx.x;
    const int w    = tid >> 5;
    const int lane = tid & 31;
    const int g    = lane >> 2;
    const int t    = lane & 3;

    const uint32_t kH = smem_u32(sKhi), kL = smem_u32(sKlo);
    const uint32_t vH = smem_u32(sVhi), vL = smem_u32(sVlo);
    const int lrow = (lane & 7) * 36;
    const int lm   = (lane >> 3) * 4;
    const int vrow = (((lane >> 3) & 1) * 8 + (lane & 7)) * 36;
    const int vd   = (lane >> 4) * 4;

    uint32_t qhi[4][4], qlo[4][4];
    {
        const float* r0 = qbase + (size_t)(w * 16 + g) * 64;
        const float* r1 = r0 + 8 * 64;
        #pragma unroll
        for (int ks = 0; ks < 4; ++ks) {
            float2 x0 = *(const float2*)(r0 + ks * 16 + 2 * t);
            float2 x1 = *(const float2*)(r1 + ks * 16 + 2 * t);
            float2 x2 = *(const float2*)(r0 + ks * 16 + 8 + 2 * t);
            float2 x3 = *(const float2*)(r1 + ks * 16 + 8 + 2 * t);
            float f[8] = {x0.x, x0.y, x1.x, x1.y, x2.x, x2.y, x3.x, x3.y};
            #pragma unroll
            for (int i = 0; i < 8; ++i) f[i] *= 0.125f;
            float hi[8], lo[8];
            #pragma unroll
            for (int i = 0; i < 8; ++i) {
                hi[i] = __bfloat162float(__float2bfloat16(f[i]));
                lo[i] = f[i] - hi[i];
            }
            #pragma unroll
            for (int r = 0; r < 4; ++r) {
                qhi[ks][r] = pack_bf16(hi[2*r], hi[2*r+1]);
                qlo[ks][r] = pack_bf16(lo[2*r], lo[2*r+1]);
            }
        }
    }

    float O[8][4];
    #pragma unroll
    for (int i = 0; i < 8; ++i)
        #pragma unroll
        for (int j = 0; j < 4; ++j) O[i][j] = 0.f;
    float mI[2] = {-3.0e38f, -3.0e38f};
    float lI[2] = {0.f, 0.f};

    for (int kt = 0; kt <= qt; ++kt) {
        const size_t tb = kvbase + (size_t)kt * 64 * 64;
        __syncthreads();
        #pragma unroll
        for (int it = 0; it < 4; ++it) {
            int idx = tid + it * 128;
            int row = idx >> 3, c8 = idx & 7;
            size_t go = tb + row * 64 + c8 * 8;
            int so = row * 36 + c8 * 4;
            *(uint4*)&sKhi[so] = *(const uint4*)(Khi + go);
            *(uint4*)&sKlo[so] = *(const uint4*)(Klo + go);
            *(uint4*)&sVhi[so] = *(const uint4*)(Vhi + go);
            *(uint4*)&sVlo[so] = *(const uint4*)(Vlo + go);
        }
        __syncthreads();

        float S[8][4];
        #pragma unroll
        for (int nt = 0; nt < 8; ++nt) {
            float* sa = S[nt];
            sa[0] = sa[1] = sa[2] = sa[3] = 0.f;
            uint32_t bh[8], bl[8];
            const int wo = nt * 288 + lrow + lm;
            ldsm4(bh,     kH + wo * 4);
            ldsm4(bh + 4, kH + (wo + 16) * 4);
            ldsm4(bl,     kL + wo * 4);
            ldsm4(bl + 4, kL + (wo + 16) * 4);
            #pragma unroll
            for (int ks = 0; ks < 4; ++ks) {
                mma16816(sa, qhi[ks], bh + 2 * ks);
                mma16816(sa, qlo[ks], bh + 2 * ks);
                mma16816(sa, qhi[ks], bl + 2 * ks);
            }
        }

        if (kt == qt) {
            const int rg0 = w * 16 + g;
            #pragma unroll
            for (int nt = 0; nt < 8; ++nt) {
                int c0 = nt * 8 + 2 * t;
                if (c0 > rg0)     S[nt][0] = -1e30f;
                if (c0 + 1 > rg0) S[nt][1] = -1e30f;
                if (c0 > rg0 + 8)     S[nt][2] = -1e30f;
                if (c0 + 1 > rg0 + 8) S[nt][3] = -1e30f;
            }
        }

        float mt0 = -3.0e38f, mt1 = -3.0e38f;
        #pragma unroll
        for (int nt = 0; nt < 8; ++nt) {
            mt0 = fmaxf(mt0, fmaxf(S[nt][0], S[nt][1]));
            mt1 = fmaxf(mt1, fmaxf(S[nt][2], S[nt][3]));
        }
        mt0 = fmaxf(mt0, __shfl_xor_sync(0xffffffffu, mt0, 1));
        mt0 = fmaxf(mt0, __shfl_xor_sync(0xffffffffu, mt0, 2));
        mt1 = fmaxf(mt1, __shfl_xor_sync(0xffffffffu, mt1, 1));
        mt1 = fmaxf(mt1, __shfl_xor_sync(0xffffffffu, mt1, 2));
        float mn0 = fmaxf(mI[0], mt0), mn1 = fmaxf(mI[1], mt1);
        float al0 = __expf(mI[0] - mn0), al1 = __expf(mI[1] - mn1);
        mI[0] = mn0; mI[1] = mn1;

        float sum0 = 0.f, sum1 = 0.f;
        #pragma unroll
        for (int nt = 0; nt < 8; ++nt) {
            S[nt][0] = __expf(S[nt][0] - mn0); sum0 += S[nt][0];
            S[nt][1] = __expf(S[nt][1] - mn0); sum0 += S[nt][1];
            S[nt][2] = __expf(S[nt][2] - mn1); sum1 += S[nt][2];
            S[nt][3] = __expf(S[nt][3] - mn1); sum1 += S[nt][3];
        }
        sum0 += __shfl_xor_sync(0xffffffffu, sum0, 1);
        sum0 += __shfl_xor_sync(0xffffffffu, sum0, 2);
        sum1 += __shfl_xor_sync(0xffffffffu, sum1, 1);
        sum1 += __shfl_xor_sync(0xffffffffu, sum1, 2);
        lI[0] = lI[0] * al0 + sum0;
        lI[1] = lI[1] * al1 + sum1;
        #pragma unroll
        for (int dt = 0; dt < 8; ++dt) {
            O[dt][0] *= al0; O[dt][1] *= al0;
            O[dt][2] *= al1; O[dt][3] *= al1;
        }

        uint32_t phi[8][2], plo[8][2];
        #pragma unroll
        for (int nt = 0; nt < 8; ++nt) {
            float h0 = __bfloat162float(__float2bfloat16(S[nt][0]));
            float h1 = __bfloat162float(__float2bfloat16(S[nt][1]));
            float h2 = __bfloat162float(__float2bfloat16(S[nt][2]));
            float h3 = __bfloat162float(__float2bfloat16(S[nt][3]));
            phi[nt][0] = pack_bf16(h0, h1);
            phi[nt][1] = pack_bf16(h2, h3);
            plo[nt][0] = pack_bf16(S[nt][0] - h0, S[nt][1] - h1);
            plo[nt][1] = pack_bf16(S[nt][2] - h2, S[nt][3] - h3);
        }

        #pragma unroll
        for (int ks = 0; ks < 4; ++ks) {
            uint32_t aP[4] = {phi[2*ks][0], phi[2*ks][1], phi[2*ks+1][0], phi[2*ks+1][1]};
            uint32_t aL[4] = {plo[2*ks][0], plo[2*ks][1], plo[2*ks+1][0], plo[2*ks+1][1]};
            #pragma unroll
            for (int dp = 0; dp < 4; ++dp) {
                uint32_t vh[4], vl[4];
                const int wo = ks * 576 + vrow + dp * 8 + vd;
                ldsm4t(vh, vH + wo * 4);
                ldsm4t(vl, vL + wo * 4);
                mma16816(O[2*dp],     aP, vh);
                mma16816(O[2*dp],     aL, vh);
                mma16816(O[2*dp],     aP, vl);
                mma16816(O[2*dp + 1], aP, vh + 2);
                mma16816(O[2*dp + 1], aL, vh + 2);
                mma16816(O[2*dp + 1], aP, vl + 2);
            }
        }
    }

    // ---- epilogue: normalize, add v_res (xout cols 448+), write [BT,512] ----
    const float inv0 = 1.0f / lI[0];
    const float inv1 = 1.0f / lI[1];
    const size_t row0 = (size_t)b * Tt + qt * 64 + w * 16 + g;
    const size_t row1 = row0 + 8;
    #pragma unroll
    for (int dt = 0; dt < 8; ++dt) {
        const int col = h * 64 + dt * 8 + 2 * t;
        float2 vr0 = *(const float2*)(xout + row0 * 960 + 448 + col);
        float2 vr1 = *(const float2*)(xout + row1 * 960 + 448 + col);
        float2 o0 = make_float2(O[dt][0] * inv0 + vr0.x, O[dt][1] * inv0 + vr0.y);
        float2 o1 = make_float2(O[dt][2] * inv1 + vr1.x, O[dt][3] * inv1 + vr1.y);
        *(float2*)(out + row0 * 512 + col) = o0;
        *(float2*)(out + row1 * 512 + col) = o1;
    }
}

// ---------------------------------------------------------------------------
extern "C" void kernel_launch(void* const* d_in, const int* in_sizes, int n_in,
                              void* d_out, int out_size)
{
    const float* x    = (const float*)d_in[0];
    const float* WDQ  = (const float*)d_in[1];
    const float* WUQ  = (const float*)d_in[2];
    const float* WQR  = (const float*)d_in[3];
    const float* WDKV = (const float*)d_in[4];
    const float* WUK  = (const float*)d_in[5];
    const float* WUV  = (const float*)d_in[6];
    const float* WKR  = (const float*)d_in[7];
    const float* WVR  = (const float*)d_in[8];
    const float* WO   = (const float*)d_in[9];
    const float* qlnw = (const float*)d_in[10];
    const float* kvlnw= (const float*)d_in[11];
    const float* qhw  = (const float*)d_in[12];
    const float* khw  = (const float*)d_in[13];
    float* out = (float*)d_out;

    float *xout, *q2, *kv2, *q, *ao;
    __nv_bfloat16 *khi, *klo, *vhi, *vlo, *ahi, *alo, *whi, *wlo;
    cudaGetSymbolAddress((void**)&xout, g_xout);
    cudaGetSymbolAddress((void**)&q2,   g_q2);
    cudaGetSymbolAddress((void**)&kv2,  g_kv2);
    cudaGetSymbolAddress((void**)&q,    g_q);
    cudaGetSymbolAddress((void**)&ao,   g_ao);
    cudaGetSymbolAddress((void**)&khi,  g_khi);
    cudaGetSymbolAddress((void**)&klo,  g_klo);
    cudaGetSymbolAddress((void**)&vhi,  g_vhi);
    cudaGetSymbolAddress((void**)&vlo,  g_vlo);
    cudaGetSymbolAddress((void**)&ahi,  g_ahi);
    cudaGetSymbolAddress((void**)&alo,  g_alo);
    cudaGetSymbolAddress((void**)&whi,  g_whi);
    cudaGetSymbolAddress((void**)&wlo,  g_wlo);

    // ---- weights: one batched transpose+split launch (fused-group offsets) ----
    {
        TJobs jb;
        const float* Ws[9] = {WDQ, WDKV, WKR, WVR, WUQ, WQR, WUK, WUV, WO};
        const int Ks[9]    = {512, 512,  512, 512, 256, 256, 128, 128, 512};
        const int Ns[9]    = {256, 128,  64,  512, 256, 256, 64,  128, 512};
        const int Os[9]    = {OFF_DQ, OFF_DKV, OFF_KR, OFF_VR, OFF_UQ,
                              OFF_QR, OFF_UK, OFF_UV, OFF_WO};
        int acc = 0;
        for (int i = 0; i < 9; ++i) {
            jb.W[i] = Ws[i]; jb.K[i] = Ks[i]; jb.N[i] = Ns[i]; jb.woff[i] = Os[i];
            jb.t0[i] = acc;
            acc += (Ks[i] / 32) * (Ns[i] / 32);
        }
        jb.t0[9] = acc;
        transpose_split_all<<<acc, dim3(32, 8)>>>(jb, whi, wlo);
    }

    // ---- X-group: split x once, one fused GEMM (N=960) ----
    split_act<<<BT*512/1024, 256>>>(x, ahi, alo);
    hgemm<64><<<dim3(15, 64), 256>>>(ahi, alo, whi + OFF_X, wlo + OFF_X,
                                     xout, BT, 960, 512);

    // ---- Q path: rms(cq) -> split -> fused UQ|QR (N=512) ----
    rms_strided<<<BT, 128>>>(xout, qlnw, 256, 960, 0);
    split_act_strided<<<BT*256/1024, 256>>>(xout, 960, 0, 256, ahi, alo);
    hgemm<64><<<dim3(8, 64), 256>>>(ahi, alo, whi + OFF_CQ, wlo + OFF_CQ,
                                    q2, BT, 512, 256);

    // ---- KV path: rms(ckv) -> split -> fused UK|UV (N=192) ----
    rms_strided<<<BT, 128>>>(xout, kvlnw, 128, 960, 256);
    split_act_strided<<<BT*128/1024, 256>>>(xout, 960, 256, 128, ahi, alo);
    hgemm<64><<<dim3(3, 64), 256>>>(ahi, alo, whi + OFF_CKV, wlo + OFF_CKV,
                                    kv2, BT, 192, 128);

    // ---- rope + head-norm + layout ----
    assemble<<<dim3(Tt, Bb), 256>>>(q2, kv2, xout, qhw, khw,
                                    q, khi, klo, vhi, vlo);
    // ---- causal flash attention (+ residual add from xout) ----
    flash_mma<<<dim3(Tt/64, Hh, Bb), 128>>>(q, khi, klo, vhi, vlo, xout, ao);
    // ---- output projection ----
    split_act<<<BT*512/1024, 256>>>(ao, ahi, alo);
    hgemm<64><<<dim3(8, 64), 256>>>(ahi, alo, whi + OFF_WO, wlo + OFF_WO,
                                    out, BT, 512, 512);
}

// round 10
// speedup vs baseline: 1.1055x; 1.1055x over previous
#include <cuda_runtime.h>
#include <cuda_bf16.h>
#include <math.h>
#include <cstdint>
#include <cstring>

// ---------------------------------------------------------------------------
// MLA attention pipeline. B=4, T=2048, D=512, H=8, KVH=2, HD=64
// Round 10: fused GEMM groups restored to BN=128 via zero-padded weight rows
// (X-group N=1024: cq|ckv|kr|pad|vres); flash gets cp.async double-buffered
// K/V tiles (2x36KB stages) to overlap tile loads with compute.
// ---------------------------------------------------------------------------

#define Bb   4
#define Tt   2048
#define Hh   8
#define KVHh 2
#define BT   (Bb*Tt)      // 8192
#define EPSF 1e-6f

// ------------------------- scratch (device globals) ------------------------
__device__ float g_xout[BT*1024];  // cq|ckv|kr|pad|vres (cols 0|256|384|448|512)
__device__ float g_q2  [BT*512];   // qn|qr
__device__ float g_kv2 [BT*192];   // kn|vraw
__device__ float g_q   [BT*512];   // [B,H,T,64] fp32
__device__ float g_ao  [BT*512];

__device__ __nv_bfloat16 g_khi[Bb*KVHh*Tt*64];
__device__ __nv_bfloat16 g_klo[Bb*KVHh*Tt*64];
__device__ __nv_bfloat16 g_vhi[Bb*KVHh*Tt*64];
__device__ __nv_bfloat16 g_vlo[Bb*KVHh*Tt*64];

__device__ __nv_bfloat16 g_ahi[BT*512];
__device__ __nv_bfloat16 g_alo[BT*512];

// fused weight groups, [N][K] row-stacked (pad rows = untouched BSS zeros)
#define OFF_X    0
#define OFF_DQ   0
#define OFF_DKV  131072     // row 256 * 512
#define OFF_KR   196608     // row 384 * 512
// pad rows 448..512 (zeros)
#define OFF_VR   262144     // row 512 * 512
#define OFF_CQ   524288     // 1024*512
#define OFF_UQ   524288
#define OFF_QR   589824     // +256*256
#define OFF_CKV  655360
#define OFF_UK   655360
#define OFF_UV   663552     // +64*128
#define OFF_WO   679936     // +128*128
#define WT_TOT   942080
__device__ __nv_bfloat16 g_whi[WT_TOT];
__device__ __nv_bfloat16 g_wlo[WT_TOT];

// ------------------------- PTX helpers -------------------------------------
__device__ __forceinline__ void mma16816(
    float* d, const uint32_t* a, const uint32_t* b)
{
    asm volatile(
        "mma.sync.aligned.m16n8k16.row.col.f32.bf16.bf16.f32 "
        "{%0,%1,%2,%3}, {%4,%5,%6,%7}, {%8,%9}, {%0,%1,%2,%3};"
        : "+f"(d[0]), "+f"(d[1]), "+f"(d[2]), "+f"(d[3])
        : "r"(a[0]), "r"(a[1]), "r"(a[2]), "r"(a[3]), "r"(b[0]), "r"(b[1]));
}

__device__ __forceinline__ void ldsm4(uint32_t* r, uint32_t addr) {
    asm volatile("ldmatrix.sync.aligned.m8n8.x4.shared.b16 {%0,%1,%2,%3}, [%4];"
        : "=r"(r[0]), "=r"(r[1]), "=r"(r[2]), "=r"(r[3]) : "r"(addr));
}
__device__ __forceinline__ void ldsm4t(uint32_t* r, uint32_t addr) {
    asm volatile("ldmatrix.sync.aligned.m8n8.x4.trans.shared.b16 {%0,%1,%2,%3}, [%4];"
        : "=r"(r[0]), "=r"(r[1]), "=r"(r[2]), "=r"(r[3]) : "r"(addr));
}

__device__ __forceinline__ uint32_t smem_u32(const void* p) {
    uint32_t a;
    asm("{ .reg .u64 t; cvta.to.shared.u64 t, %1; cvt.u32.u64 %0, t; }"
        : "=r"(a) : "l"(p));
    return a;
}

#define CP_ASYNC16(saddr, gptr) \
    asm volatile("cp.async.cg.shared.global [%0], [%1], 16;" \
                 :: "r"(saddr), "l"(gptr) : "memory")
#define CP_COMMIT() asm volatile("cp.async.commit_group;" ::: "memory")
#define CP_WAIT(n)  asm volatile("cp.async.wait_group %0;" :: "n"(n) : "memory")

__device__ __forceinline__ uint32_t pack_bf16(float lo, float hi) {
    __nv_bfloat162 p = __floats2bfloat162_rn(lo, hi);
    uint32_t u; memcpy(&u, &p, 4);
    return u;
}

// ---------------------------------------------------------------------------
// Batched transpose + bf16 hi/lo split: 9 weights in one launch.
// ---------------------------------------------------------------------------
struct TJobs {
    const float* W[9];
    int K[9], N[9], woff[9];
    int t0[10];
};

__global__ void transpose_split_all(
    TJobs jb, __nv_bfloat16* __restrict__ hi, __nv_bfloat16* __restrict__ lo)
{
    __shared__ float t[32][33];
    const int bid = blockIdx.x;
    int j = 0;
    #pragma unroll
    for (int i = 0; i < 8; ++i) if (bid >= jb.t0[i + 1]) j = i + 1;
    const int tile = bid - jb.t0[j];
    const int K = jb.K[j], N = jb.N[j];
    const int ntx = N / 32;
    const int n0 = (tile % ntx) * 32, k0 = (tile / ntx) * 32;
    const float* W = jb.W[j];
    __nv_bfloat16* ho = hi + jb.woff[j];
    __nv_bfloat16* lp = lo + jb.woff[j];

    for (int r = threadIdx.y; r < 32; r += 8)
        t[r][threadIdx.x] = W[(size_t)(k0 + r) * N + n0 + threadIdx.x];
    __syncthreads();
    for (int r = threadIdx.y; r < 32; r += 8) {
        float v = t[threadIdx.x][r];
        __nv_bfloat16 h = __float2bfloat16(v);
        __nv_bfloat16 l = __float2bfloat16(v - __bfloat162float(h));
        ho[(size_t)(n0 + r) * K + k0 + threadIdx.x] = h;
        lp[(size_t)(n0 + r) * K + k0 + threadIdx.x] = l;
    }
}

// ---------------------------------------------------------------------------
// fp32 -> bf16 hi/lo splits.
// ---------------------------------------------------------------------------
__global__ __launch_bounds__(256) void split_act(
    const float* __restrict__ x, __nv_bfloat16* __restrict__ hi,
    __nv_bfloat16* __restrict__ lo)
{
    const size_t job = (size_t)blockIdx.x * 256 + threadIdx.x;
    float4 v = *(const float4*)(x + job * 4);
    float h0 = __bfloat162float(__float2bfloat16(v.x));
    float h1 = __bfloat162float(__float2bfloat16(v.y));
    float h2 = __bfloat162float(__float2bfloat16(v.z));
    float h3 = __bfloat162float(__float2bfloat16(v.w));
    uint2 ph = make_uint2(pack_bf16(h0, h1), pack_bf16(h2, h3));
    uint2 pl = make_uint2(pack_bf16(v.x - h0, v.y - h1), pack_bf16(v.z - h2, v.w - h3));
    *(uint2*)((uint32_t*)hi + job * 2) = ph;
    *(uint2*)((uint32_t*)lo + job * 2) = pl;
}

__global__ __launch_bounds__(256) void split_act_strided(
    const float* __restrict__ src, int stride, int col0, int dim,
    __nv_bfloat16* __restrict__ hi, __nv_bfloat16* __restrict__ lo)
{
    const size_t job = (size_t)blockIdx.x * 256 + threadIdx.x;
    const size_t idx = job * 4;
    const int row = (int)(idx / dim), col = (int)(idx % dim);
    float4 v = *(const float4*)(src + (size_t)row * stride + col0 + col);
    float h0 = __bfloat162float(__float2bfloat16(v.x));
    float h1 = __bfloat162float(__float2bfloat16(v.y));
    float h2 = __bfloat162float(__float2bfloat16(v.z));
    float h3 = __bfloat162float(__float2bfloat16(v.w));
    uint2 ph = make_uint2(pack_bf16(h0, h1), pack_bf16(h2, h3));
    uint2 pl = make_uint2(pack_bf16(v.x - h0, v.y - h1), pack_bf16(v.z - h2, v.w - h3));
    *(uint2*)((uint32_t*)hi + job * 2) = ph;
    *(uint2*)((uint32_t*)lo + job * 2) = pl;
}

// ---------------------------------------------------------------------------
// HMMA GEMM (verified R8 kernel, unchanged math).
// ---------------------------------------------------------------------------
template <int BN>
__global__ __launch_bounds__(256) void hgemm(
    const __nv_bfloat16* __restrict__ Ahi, const __nv_bfloat16* __restrict__ Alo,
    const __nv_bfloat16* __restrict__ Whi, const __nv_bfloat16* __restrict__ Wlo,
    float* __restrict__ C, int M, int N, int K)
{
    __shared__ uint32_t sBhi[BN * 36];
    __shared__ uint32_t sBlo[BN * 36];

    const int bm = blockIdx.y * 128;
    const int bn = blockIdx.x * BN;
    const int tid = threadIdx.x;
    const int w = tid >> 5, lane = tid & 31;
    const int g = lane >> 2, t = lane & 3;
    constexpr int NT = BN / 8;
    constexpr int NJ = BN / 32;

    const uint32_t bH = smem_u32(sBhi);
    const uint32_t bL = smem_u32(sBlo);
    const int lrow = (lane & 7) * 36;
    const int lm   = (lane >> 3) * 4;

    float acc[NT][4];
    #pragma unroll
    for (int nt = 0; nt < NT; ++nt)
        #pragma unroll
        for (int j = 0; j < 4; ++j) acc[nt][j] = 0.f;

    const int r0 = bm + w * 16 + g;

    int jn[NJ], jc[NJ];
    #pragma unroll
    for (int i = 0; i < NJ; ++i) { int j = tid + i * 256; jn[i] = j >> 3; jc[i] = j & 7; }

    uint4 pfh[NJ], pfl[NJ];
    #pragma unroll
    for (int i = 0; i < NJ; ++i) {
        size_t go = (size_t)(bn + jn[i]) * K + jc[i] * 8;
        pfh[i] = *(const uint4*)(Whi + go);
        pfl[i] = *(const uint4*)(Wlo + go);
    }

    const int nchunk = K >> 6;
    for (int ch = 0; ch < nchunk; ++ch) {
        __syncthreads();
        #pragma unroll
        for (int i = 0; i < NJ; ++i) {
            *(uint4*)&sBhi[jn[i] * 36 + jc[i] * 4] = pfh[i];
            *(uint4*)&sBlo[jn[i] * 36 + jc[i] * 4] = pfl[i];
        }
        __syncthreads();
        if (ch + 1 < nchunk) {
            #pragma unroll
            for (int i = 0; i < NJ; ++i) {
                size_t go = (size_t)(bn + jn[i]) * K + (ch + 1) * 64 + jc[i] * 8;
                pfh[i] = *(const uint4*)(Whi + go);
                pfl[i] = *(const uint4*)(Wlo + go);
            }
        }

        uint32_t ahi[4][4], alo[4][4];
        {
            const size_t base0 = (size_t)r0 * K + ch * 64;
            const size_t base1 = base0 + 8 * (size_t)K;
            #pragma unroll
            for (int ks = 0; ks < 4; ++ks) {
                int c = ks * 16 + 2 * t;
                ahi[ks][0] = *(const uint32_t*)(Ahi + base0 + c);
                ahi[ks][1] = *(const uint32_t*)(Ahi + base1 + c);
                ahi[ks][2] = *(const uint32_t*)(Ahi + base0 + c + 8);
                ahi[ks][3] = *(const uint32_t*)(Ahi + base1 + c + 8);
                alo[ks][0] = *(const uint32_t*)(Alo + base0 + c);
                alo[ks][1] = *(const uint32_t*)(Alo + base1 + c);
                alo[ks][2] = *(const uint32_t*)(Alo + base0 + c + 8);
                alo[ks][3] = *(const uint32_t*)(Alo + base1 + c + 8);
            }
        }

        #pragma unroll
        for (int nt = 0; nt < NT; ++nt) {
            uint32_t bh[8], bl[8];
            const int wo = nt * 288 + lrow + lm;
            ldsm4(bh,     bH + wo * 4);
            ldsm4(bh + 4, bH + (wo + 16) * 4);
            ldsm4(bl,     bL + wo * 4);
            ldsm4(bl + 4, bL + (wo + 16) * 4);
            #pragma unroll
            for (int ks = 0; ks < 4; ++ks) {
                mma16816(acc[nt], ahi[ks], bh + 2 * ks);
                mma16816(acc[nt], alo[ks], bh + 2 * ks);
                mma16816(acc[nt], ahi[ks], bl + 2 * ks);
            }
        }
    }

    #pragma unroll
    for (int nt = 0; nt < NT; ++nt) {
        const int col = bn + nt * 8 + 2 * t;
        *(float2*)(C + (size_t)r0 * N + col)       = make_float2(acc[nt][0], acc[nt][1]);
        *(float2*)(C + (size_t)(r0 + 8) * N + col) = make_float2(acc[nt][2], acc[nt][3]);
    }
}

// ---------------------------------------------------------------------------
// In-place strided RMSNorm.
// ---------------------------------------------------------------------------
__global__ __launch_bounds__(128) void rms_strided(
    float* __restrict__ x, const float* __restrict__ w,
    int dim, int stride, int col0)
{
    const int row = blockIdx.x;
    float* xr = x + (size_t)row * stride + col0;
    float ss = 0.f;
    for (int i = threadIdx.x; i < dim; i += 128) { float v = xr[i]; ss += v * v; }
    #pragma unroll
    for (int off = 16; off; off >>= 1) ss += __shfl_xor_sync(0xffffffffu, ss, off);
    __shared__ float sred[4];
    if ((threadIdx.x & 31) == 0) sred[threadIdx.x >> 5] = ss;
    __syncthreads();
    float tot = sred[0] + sred[1] + sred[2] + sred[3];
    float rr = rsqrtf(tot / (float)dim + EPSF);
    for (int i = threadIdx.x; i < dim; i += 128) xr[i] = xr[i] * rr * w[i];
}

// ---------------------------------------------------------------------------
// Assemble: RoPE + concat + per-head RMSNorm (xout stride 1024, kr col 384).
// ---------------------------------------------------------------------------
__global__ __launch_bounds__(256) void assemble(
    const float* __restrict__ q2, const float* __restrict__ kv2,
    const float* __restrict__ xout,
    const float* __restrict__ qhw, const float* __restrict__ khw,
    float* __restrict__ q,
    __nv_bfloat16* __restrict__ khi, __nv_bfloat16* __restrict__ klo,
    __nv_bfloat16* __restrict__ vhi, __nv_bfloat16* __restrict__ vlo)
{
    const int t = blockIdx.x, b = blockIdx.y;
    const int row = b * Tt + t;
    const int w = threadIdx.x >> 5, lane = threadIdx.x & 31;

    const int fi = lane & 15;
    float invf = (float)exp(-((double)fi / 16.0) * log(500000.0));
    float ph = (float)t * invf;
    float sv, cv;
    sincosf(ph, &sv, &cv);

    {
        const int h = w;
        const float* qnr = q2 + (size_t)row * 512 + h * 32;
        const float* qrr = q2 + (size_t)row * 512 + 256 + h * 32;
        float v0 = qnr[lane];
        float x1 = qrr[lane];
        float xr_ = (lane < 16) ? -qrr[lane + 16] : qrr[lane - 16];
        float v1 = x1 * cv + xr_ * sv;
        float ss = v0 * v0 + v1 * v1;
        #pragma unroll
        for (int off = 16; off; off >>= 1) ss += __shfl_xor_sync(0xffffffffu, ss, off);
        float rr = rsqrtf(ss / 64.0f + EPSF);
        float* qo = q + ((size_t)(b * Hh + h) * Tt + t) * 64;
        qo[lane]      = v0 * rr * qhw[lane];
        qo[lane + 32] = v1 * rr * qhw[lane + 32];
    }

    if (w < KVHh) {
        const int kvh = w;
        const float* knr = kv2 + (size_t)row * 192 + kvh * 32;
        const float* krr = xout + (size_t)row * 1024 + 384 + kvh * 32;
        float v0 = knr[lane];
        float x1 = krr[lane];
        float xr_ = (lane < 16) ? -krr[lane + 16] : krr[lane - 16];
        float v1 = x1 * cv + xr_ * sv;
        float ss = v0 * v0 + v1 * v1;
        #pragma unroll
        for (int off = 16; off; off >>= 1) ss += __shfl_xor_sync(0xffffffffu, ss, off);
        float rr = rsqrtf(ss / 64.0f + EPSF);
        float k0 = v0 * rr * khw[lane];
        float k1 = v1 * rr * khw[lane + 32];
        size_t ko = ((size_t)(b * KVHh + kvh) * Tt + t) * 64;
        float h0 = __bfloat162float(__float2bfloat16(k0));
        float h1 = __bfloat162float(__float2bfloat16(k1));
        khi[ko + lane]      = __float2bfloat16(h0);
        khi[ko + lane + 32] = __float2bfloat16(h1);
        klo[ko + lane]      = __float2bfloat16(k0 - h0);
        klo[ko + lane + 32] = __float2bfloat16(k1 - h1);
    }

    for (int i = threadIdx.x; i < 128; i += 256) {
        int kvh = i >> 6, d = i & 63;
        float val = kv2[(size_t)row * 192 + 64 + i];
        float h = __bfloat162float(__float2bfloat16(val));
        size_t o = ((size_t)(b * KVHh + kvh) * Tt + t) * 64 + d;
        vhi[o] = __float2bfloat16(h);
        vlo[o] = __float2bfloat16(val - h);
    }
}

// ---------------------------------------------------------------------------
// Flash attention: HMMA + ldmatrix + cp.async double-buffered K/V tiles.
// Dynamic smem: 2 stages x 4 arrays x 2304 words = 73728 B.
// Grid (T/64, H, B), 128 threads, heavy-first qt ordering.
// ---------------------------------------------------------------------------
__device__ __forceinline__ void flash_issue_tile(
    int tid, uint32_t sbase, size_t tb,
    const __nv_bfloat16* Khi, const __nv_bfloat16* Klo,
    const __nv_bfloat16* Vhi, const __nv_bfloat16* Vlo)
{
    #pragma unroll
    for (int it = 0; it < 4; ++it) {
        int idx = tid + it * 128;
        int row = idx >> 3, c8 = idx & 7;
        size_t go = tb + row * 64 + c8 * 8;
        uint32_t so = (uint32_t)(row * 36 + c8 * 4) * 4;
        CP_ASYNC16(sbase + so,             Khi + go);
        CP_ASYNC16(sbase + 9216  + so,     Klo + go);
        CP_ASYNC16(sbase + 18432 + so,     Vhi + go);
        CP_ASYNC16(sbase + 27648 + so,     Vlo + go);
    }
}

__global__ __launch_bounds__(128) void flash_mma(
    const float* __restrict__ Q,
    const __nv_bfloat16* __restrict__ Khi, const __nv_bfloat16* __restrict__ Klo,
    const __nv_bfloat16* __restrict__ Vhi, const __nv_bfloat16* __restrict__ Vlo,
    const float* __restrict__ xout, float* __restrict__ out)
{
    extern __shared__ uint32_t dsm[];
    const uint32_t sb = smem_u32(dsm);

    const int qt = (Tt / 64 - 1) - blockIdx.x;
    const int h = blockIdx.y, b = blockIdx.z;
    const int kvh = h >> 2;
    const float* qbase = Q + (((size_t)b * Hh + h) * Tt + qt * 64) * 64;
    const size_t kvbase = ((size_t)(b * KVHh + kvh) * Tt) * 64;

    const int tid  = threadIdx.x;
    const int w    = tid >> 5;
    const int lane = tid & 31;
    const int g    = lane >> 2;
    const int t    = lane & 3;

    const int lrow = (lane & 7) * 36;
    const int lm   = (lane >> 3) * 4;
    const int vrow = (((lane >> 3) & 1) * 8 + (lane & 7)) * 36;
    const int vd   = (lane >> 4) * 4;

    // ---- Q fragments (built once), hi+lo split ----
    uint32_t qhi[4][4], qlo[4][4];
    {
        const float* r0 = qbase + (size_t)(w * 16 + g) * 64;
        const float* r1 = r0 + 8 * 64;
        #pragma unroll
        for (int ks = 0; ks < 4; ++ks) {
            float2 x0 = *(const float2*)(r0 + ks * 16 + 2 * t);
            float2 x1 = *(const float2*)(r1 + ks * 16 + 2 * t);
            float2 x2 = *(const float2*)(r0 + ks * 16 + 8 + 2 * t);
            float2 x3 = *(const float2*)(r1 + ks * 16 + 8 + 2 * t);
            float f[8] = {x0.x, x0.y, x1.x, x1.y, x2.x, x2.y, x3.x, x3.y};
            #pragma unroll
            for (int i = 0; i < 8; ++i) f[i] *= 0.125f;
            float hi[8], lo[8];
            #pragma unroll
            for (int i = 0; i < 8; ++i) {
                hi[i] = __bfloat162float(__float2bfloat16(f[i]));
                lo[i] = f[i] - hi[i];
            }
            #pragma unroll
            for (int r = 0; r < 4; ++r) {
                qhi[ks][r] = pack_bf16(hi[2*r], hi[2*r+1]);
                qlo[ks][r] = pack_bf16(lo[2*r], lo[2*r+1]);
            }
        }
    }

    float O[8][4];
    #pragma unroll
    for (int i = 0; i < 8; ++i)
        #pragma unroll
        for (int j = 0; j < 4; ++j) O[i][j] = 0.f;
    float mI[2] = {-3.0e38f, -3.0e38f};
    float lI[2] = {0.f, 0.f};

    // prologue: async-load tile 0 into stage 0
    flash_issue_tile(tid, sb, kvbase, Khi, Klo, Vhi, Vlo);
    CP_COMMIT();

    for (int kt = 0; kt <= qt; ++kt) {
        const int st = kt & 1;
        __syncthreads();   // all threads done computing with stage st^1
        if (kt < qt) {
            flash_issue_tile(tid, sb + (st ^ 1) * 36864,
                             kvbase + (size_t)(kt + 1) * 4096, Khi, Klo, Vhi, Vlo);
            CP_COMMIT();
            CP_WAIT(1);    // tile kt landed; tile kt+1 still in flight
        } else {
            CP_WAIT(0);
        }
        __syncthreads();

        const uint32_t kH = sb + st * 36864;
        const uint32_t kL = kH + 9216;
        const uint32_t vH = kH + 18432;
        const uint32_t vL = kH + 27648;

        // ---- S = Q K^T ----
        float S[8][4];
        #pragma unroll
        for (int nt = 0; nt < 8; ++nt) {
            float* sa = S[nt];
            sa[0] = sa[1] = sa[2] = sa[3] = 0.f;
            uint32_t bh[8], bl[8];
            const int wo = nt * 288 + lrow + lm;
            ldsm4(bh,     kH + wo * 4);
            ldsm4(bh + 4, kH + (wo + 16) * 4);
            ldsm4(bl,     kL + wo * 4);
            ldsm4(bl + 4, kL + (wo + 16) * 4);
            #pragma unroll
            for (int ks = 0; ks < 4; ++ks) {
                mma16816(sa, qhi[ks], bh + 2 * ks);
                mma16816(sa, qlo[ks], bh + 2 * ks);
                mma16816(sa, qhi[ks], bl + 2 * ks);
            }
        }

        if (kt == qt) {
            const int rg0 = w * 16 + g;
            #pragma unroll
            for (int nt = 0; nt < 8; ++nt) {
                int c0 = nt * 8 + 2 * t;
                if (c0 > rg0)     S[nt][0] = -1e30f;
                if (c0 + 1 > rg0) S[nt][1] = -1e30f;
                if (c0 > rg0 + 8)     S[nt][2] = -1e30f;
                if (c0 + 1 > rg0 + 8) S[nt][3] = -1e30f;
            }
        }

        // ---- online softmax ----
        float mt0 = -3.0e38f, mt1 = -3.0e38f;
        #pragma unroll
        for (int nt = 0; nt < 8; ++nt) {
            mt0 = fmaxf(mt0, fmaxf(S[nt][0], S[nt][1]));
            mt1 = fmaxf(mt1, fmaxf(S[nt][2], S[nt][3]));
        }
        mt0 = fmaxf(mt0, __shfl_xor_sync(0xffffffffu, mt0, 1));
        mt0 = fmaxf(mt0, __shfl_xor_sync(0xffffffffu, mt0, 2));
        mt1 = fmaxf(mt1, __shfl_xor_sync(0xffffffffu, mt1, 1));
        mt1 = fmaxf(mt1, __shfl_xor_sync(0xffffffffu, mt1, 2));
        float mn0 = fmaxf(mI[0], mt0), mn1 = fmaxf(mI[1], mt1);
        float al0 = __expf(mI[0] - mn0), al1 = __expf(mI[1] - mn1);
        mI[0] = mn0; mI[1] = mn1;

        float sum0 = 0.f, sum1 = 0.f;
        #pragma unroll
        for (int nt = 0; nt < 8; ++nt) {
            S[nt][0] = __expf(S[nt][0] - mn0); sum0 += S[nt][0];
            S[nt][1] = __expf(S[nt][1] - mn0); sum0 += S[nt][1];
            S[nt][2] = __expf(S[nt][2] - mn1); sum1 += S[nt][2];
            S[nt][3] = __expf(S[nt][3] - mn1); sum1 += S[nt][3];
        }
        sum0 += __shfl_xor_sync(0xffffffffu, sum0, 1);
        sum0 += __shfl_xor_sync(0xffffffffu, sum0, 2);
        sum1 += __shfl_xor_sync(0xffffffffu, sum1, 1);
        sum1 += __shfl_xor_sync(0xffffffffu, sum1, 2);
        lI[0] = lI[0] * al0 + sum0;
        lI[1] = lI[1] * al1 + sum1;
        #pragma unroll
        for (int dt = 0; dt < 8; ++dt) {
            O[dt][0] *= al0; O[dt][1] *= al0;
            O[dt][2] *= al1; O[dt][3] *= al1;
        }

        // ---- P fragments (C-frag -> A-frag identity), hi/lo split ----
        uint32_t phi[8][2], plo[8][2];
        #pragma unroll
        for (int nt = 0; nt < 8; ++nt) {
            float h0 = __bfloat162float(__float2bfloat16(S[nt][0]));
            float h1 = __bfloat162float(__float2bfloat16(S[nt][1]));
            float h2 = __bfloat162float(__float2bfloat16(S[nt][2]));
            float h3 = __bfloat162float(__float2bfloat16(S[nt][3]));
            phi[nt][0] = pack_bf16(h0, h1);
            phi[nt][1] = pack_bf16(h2, h3);
            plo[nt][0] = pack_bf16(S[nt][0] - h0, S[nt][1] - h1);
            plo[nt][1] = pack_bf16(S[nt][2] - h2, S[nt][3] - h3);
        }

        // ---- O += P V (V frags via ldmatrix.x4.trans) ----
        #pragma unroll
        for (int ks = 0; ks < 4; ++ks) {
            uint32_t aP[4] = {phi[2*ks][0], phi[2*ks][1], phi[2*ks+1][0], phi[2*ks+1][1]};
            uint32_t aL[4] = {plo[2*ks][0], plo[2*ks][1], plo[2*ks+1][0], plo[2*ks+1][1]};
            #pragma unroll
            for (int dp = 0; dp < 4; ++dp) {
                uint32_t vh[4], vl[4];
                const int wo = ks * 576 + vrow + dp * 8 + vd;
                ldsm4t(vh, vH + wo * 4);
                ldsm4t(vl, vL + wo * 4);
                mma16816(O[2*dp],     aP, vh);
                mma16816(O[2*dp],     aL, vh);
                mma16816(O[2*dp],     aP, vl);
                mma16816(O[2*dp + 1], aP, vh + 2);
                mma16816(O[2*dp + 1], aL, vh + 2);
                mma16816(O[2*dp + 1], aP, vl + 2);
            }
        }
    }

    // ---- epilogue: normalize, add v_res (xout cols 512+), write [BT,512] ----
    const float inv0 = 1.0f / lI[0];
    const float inv1 = 1.0f / lI[1];
    const size_t row0 = (size_t)b * Tt + qt * 64 + w * 16 + g;
    const size_t row1 = row0 + 8;
    #pragma unroll
    for (int dt = 0; dt < 8; ++dt) {
        const int col = h * 64 + dt * 8 + 2 * t;
        float2 vr0 = *(const float2*)(xout + row0 * 1024 + 512 + col);
        float2 vr1 = *(const float2*)(xout + row1 * 1024 + 512 + col);
        float2 o0 = make_float2(O[dt][0] * inv0 + vr0.x, O[dt][1] * inv0 + vr0.y);
        float2 o1 = make_float2(O[dt][2] * inv1 + vr1.x, O[dt][3] * inv1 + vr1.y);
        *(float2*)(out + row0 * 512 + col) = o0;
        *(float2*)(out + row1 * 512 + col) = o1;
    }
}

// ---------------------------------------------------------------------------
extern "C" void kernel_launch(void* const* d_in, const int* in_sizes, int n_in,
                              void* d_out, int out_size)
{
    const float* x    = (const float*)d_in[0];
    const float* WDQ  = (const float*)d_in[1];
    const float* WUQ  = (const float*)d_in[2];
    const float* WQR  = (const float*)d_in[3];
    const float* WDKV = (const float*)d_in[4];
    const float* WUK  = (const float*)d_in[5];
    const float* WUV  = (const float*)d_in[6];
    const float* WKR  = (const float*)d_in[7];
    const float* WVR  = (const float*)d_in[8];
    const float* WO   = (const float*)d_in[9];
    const float* qlnw = (const float*)d_in[10];
    const float* kvlnw= (const float*)d_in[11];
    const float* qhw  = (const float*)d_in[12];
    const float* khw  = (const float*)d_in[13];
    float* out = (float*)d_out;

    float *xout, *q2, *kv2, *q, *ao;
    __nv_bfloat16 *khi, *klo, *vhi, *vlo, *ahi, *alo, *whi, *wlo;
    cudaGetSymbolAddress((void**)&xout, g_xout);
    cudaGetSymbolAddress((void**)&q2,   g_q2);
    cudaGetSymbolAddress((void**)&kv2,  g_kv2);
    cudaGetSymbolAddress((void**)&q,    g_q);
    cudaGetSymbolAddress((void**)&ao,   g_ao);
    cudaGetSymbolAddress((void**)&khi,  g_khi);
    cudaGetSymbolAddress((void**)&klo,  g_klo);
    cudaGetSymbolAddress((void**)&vhi,  g_vhi);
    cudaGetSymbolAddress((void**)&vlo,  g_vlo);
    cudaGetSymbolAddress((void**)&ahi,  g_ahi);
    cudaGetSymbolAddress((void**)&alo,  g_alo);
    cudaGetSymbolAddress((void**)&whi,  g_whi);
    cudaGetSymbolAddress((void**)&wlo,  g_wlo);

    const int FLASH_SMEM = 73728;
    cudaFuncSetAttribute(flash_mma, cudaFuncAttributeMaxDynamicSharedMemorySize, FLASH_SMEM);

    // ---- weights: one batched transpose+split launch (padded-group offsets) ----
    {
        TJobs jb;
        const float* Ws[9] = {WDQ, WDKV, WKR, WVR, WUQ, WQR, WUK, WUV, WO};
        const int Ks[9]    = {512, 512,  512, 512, 256, 256, 128, 128, 512};
        const int Ns[9]    = {256, 128,  64,  512, 256, 256, 64,  128, 512};
        const int Os[9]    = {OFF_DQ, OFF_DKV, OFF_KR, OFF_VR, OFF_UQ,
                              OFF_QR, OFF_UK, OFF_UV, OFF_WO};
        int acc = 0;
        for (int i = 0; i < 9; ++i) {
            jb.W[i] = Ws[i]; jb.K[i] = Ks[i]; jb.N[i] = Ns[i]; jb.woff[i] = Os[i];
            jb.t0[i] = acc;
            acc += (Ks[i] / 32) * (Ns[i] / 32);
        }
        jb.t0[9] = acc;
        transpose_split_all<<<acc, dim3(32, 8)>>>(jb, whi, wlo);
    }

    // ---- X-group: split x once, one fused BN=128 GEMM (N=1024, padded) ----
    split_act<<<BT*512/1024, 256>>>(x, ahi, alo);
    hgemm<128><<<dim3(8, 64), 256>>>(ahi, alo, whi + OFF_X, wlo + OFF_X,
                                     xout, BT, 1024, 512);

    // ---- Q path: rms(cq) -> split -> fused UQ|QR (N=512) ----
    rms_strided<<<BT, 128>>>(xout, qlnw, 256, 1024, 0);
    split_act_strided<<<BT*256/1024, 256>>>(xout, 1024, 0, 256, ahi, alo);
    hgemm<128><<<dim3(4, 64), 256>>>(ahi, alo, whi + OFF_CQ, wlo + OFF_CQ,
                                     q2, BT, 512, 256);

    // ---- KV path: rms(ckv) -> split -> fused UK|UV (N=192) ----
    rms_strided<<<BT, 128>>>(xout, kvlnw, 128, 1024, 256);
    split_act_strided<<<BT*128/1024, 256>>>(xout, 1024, 256, 128, ahi, alo);
    hgemm<64><<<dim3(3, 64), 256>>>(ahi, alo, whi + OFF_CKV, wlo + OFF_CKV,
                                    kv2, BT, 192, 128);

    // ---- rope + head-norm + layout ----
    assemble<<<dim3(Tt, Bb), 256>>>(q2, kv2, xout, qhw, khw,
                                    q, khi, klo, vhi, vlo);
    // ---- causal flash attention (+ residual add from xout) ----
    flash_mma<<<dim3(Tt/64, Hh, Bb), 128, FLASH_SMEM>>>(
        q, khi, klo, vhi, vlo, xout, ao);
    // ---- output projection ----
    split_act<<<BT*512/1024, 256>>>(ao, ahi, alo);
    hgemm<128><<<dim3(4, 64), 256>>>(ahi, alo, whi + OFF_WO, wlo + OFF_WO,
                                     out, BT, 512, 512);
}